// round 2
// baseline (speedup 1.0000x reference)
#include <cuda_runtime.h>
#include <math.h>

// Problem constants
#define E   1024
#define A   64
#define H   16
#define FFD 4096
#define B   2
#define S   2048
#define M   (B*S)        // 4096 rows
#define NQKV (3*E)       // 3072

// ---------------- scratch (device globals; no allocations allowed) ----------
__device__ float g_x[M*E];
__device__ float g_wqkvT[E*NQKV];
__device__ float g_qkv[M*NQKV];
__device__ float g_q[H*B*S*A];
__device__ float g_attn[M*E];
__device__ float g_mha[M*E];
__device__ float g_hidden[M*FFD];
__device__ float g_ff[M*E];
__device__ float g_ffout[M*E];

// ---------------- elementwise add (float4) ----------------------------------
__global__ void k_add(const float4* __restrict__ a, const float4* __restrict__ b,
                      float4* __restrict__ o) {
    int i = blockIdx.x * blockDim.x + threadIdx.x;
    float4 x = a[i], y = b[i];
    x.x += y.x; x.y += y.y; x.z += y.z; x.w += y.w;
    o[i] = x;
}

// ---------------- fuse Wq/Wk/Wv [H,E,A] -> [E, 3E] --------------------------
__global__ void k_wqkv(const float* __restrict__ Wq, const float* __restrict__ Wk,
                       const float* __restrict__ Wv, float* __restrict__ out) {
    int idx = blockIdx.x * blockDim.x + threadIdx.x;
    int qkv = idx / (E*E);
    int rem = idx - qkv * (E*E);
    int h = rem / (E*A);
    int ea = rem - h * (E*A);
    int e = ea / A;
    int a = ea - e * A;
    const float* W = (qkv == 0) ? Wq : (qkv == 1) ? Wk : Wv;
    out[(size_t)e * NQKV + qkv * E + h * A + a] = W[rem];
}

// ---------------- double-buffered SGEMM 128x128x8, 8x8/thread ----------------
#define BM 128
#define BN 128
#define BK 8
#define ALD2 132   // padded A smem pitch

__global__ __launch_bounds__(256)
void k_gemm(const float* __restrict__ Ag, const float* __restrict__ Bg,
            float* __restrict__ Cg, int Md, int Nd, int Kd,
            const float* __restrict__ bias, const float* __restrict__ resid,
            int do_relu) {
    __shared__ float As[2][BK][ALD2];
    __shared__ float Bs[2][BK][BN];

    int tid = threadIdx.x;
    int tx = tid & 15, ty = tid >> 4;
    const float* Ab = Ag + (size_t)blockIdx.y * BM * Kd;
    const float* Bb = Bg + blockIdx.x * BN;

    // load mapping
    int arow = tid >> 1;             // 0..127
    int acol = (tid & 1) * 4;        // 0 or 4
    int brow = tid >> 5;             // 0..7
    int bcol = (tid & 31) * 4;       // 0..124

    float acc[8][8];
#pragma unroll
    for (int i = 0; i < 8; i++)
#pragma unroll
        for (int j = 0; j < 8; j++) acc[i][j] = 0.f;

    // prologue: load stage 0
    float4 av = *(const float4*)(Ab + (size_t)arow * Kd + acol);
    float4 bv = *(const float4*)(Bb + (size_t)brow * Nd + bcol);
    As[0][acol+0][arow] = av.x; As[0][acol+1][arow] = av.y;
    As[0][acol+2][arow] = av.z; As[0][acol+3][arow] = av.w;
    *(float4*)&Bs[0][brow][bcol] = bv;
    __syncthreads();

    int buf = 0;
    for (int k0 = BK; k0 <= Kd; k0 += BK) {
        bool more = (k0 < Kd);
        if (more) {
            av = *(const float4*)(Ab + (size_t)arow * Kd + k0 + acol);
            bv = *(const float4*)(Bb + (size_t)(k0 + brow) * Nd + bcol);
        }
#pragma unroll
        for (int k = 0; k < BK; k++) {
            float a0[4], a1[4], b0[4], b1[4];
            *(float4*)a0 = *(const float4*)&As[buf][k][ty * 4];
            *(float4*)a1 = *(const float4*)&As[buf][k][64 + ty * 4];
            *(float4*)b0 = *(const float4*)&Bs[buf][k][tx * 4];
            *(float4*)b1 = *(const float4*)&Bs[buf][k][64 + tx * 4];
#pragma unroll
            for (int i = 0; i < 4; i++)
#pragma unroll
                for (int j = 0; j < 4; j++) {
                    acc[i][j]     += a0[i] * b0[j];
                    acc[i][j+4]   += a0[i] * b1[j];
                    acc[i+4][j]   += a1[i] * b0[j];
                    acc[i+4][j+4] += a1[i] * b1[j];
                }
        }
        if (more) {
            int nb = buf ^ 1;
            As[nb][acol+0][arow] = av.x; As[nb][acol+1][arow] = av.y;
            As[nb][acol+2][arow] = av.z; As[nb][acol+3][arow] = av.w;
            *(float4*)&Bs[nb][brow][bcol] = bv;
            __syncthreads();
            buf = nb;
        }
    }

    // epilogue
#pragma unroll
    for (int half = 0; half < 2; half++) {
#pragma unroll
        for (int i = 0; i < 4; i++) {
            int row = blockIdx.y * BM + half * 64 + ty * 4 + i;
            float* cp = Cg + (size_t)row * Nd + blockIdx.x * BN;
            int c0 = tx * 4, c1 = 64 + tx * 4;
            float v[8];
#pragma unroll
            for (int j = 0; j < 8; j++) v[j] = acc[half * 4 + i][j];
            if (bias) {
#pragma unroll
                for (int j = 0; j < 4; j++) {
                    v[j]   += bias[blockIdx.x * BN + c0 + j];
                    v[j+4] += bias[blockIdx.x * BN + c1 + j];
                }
            }
            if (resid) {
                const float* rp = resid + (size_t)row * Nd + blockIdx.x * BN;
                float4 r0 = *(const float4*)(rp + c0);
                float4 r1 = *(const float4*)(rp + c1);
                v[0]+=r0.x; v[1]+=r0.y; v[2]+=r0.z; v[3]+=r0.w;
                v[4]+=r1.x; v[5]+=r1.y; v[6]+=r1.z; v[7]+=r1.w;
            }
            if (do_relu) {
#pragma unroll
                for (int j = 0; j < 8; j++) v[j] = fmaxf(v[j], 0.f);
            }
            float4 o0 = make_float4(v[0], v[1], v[2], v[3]);
            float4 o1 = make_float4(v[4], v[5], v[6], v[7]);
            *(float4*)(cp + c0) = o0;
            *(float4*)(cp + c1) = o1;
        }
    }
}

// ---------------- scatter fused qkv -> Q scratch, K/V into d_out ------------
__global__ void k_scatter(const float* __restrict__ qkv, float* __restrict__ q,
                          float* __restrict__ kout, float* __restrict__ vout) {
    int idx = blockIdx.x * blockDim.x + threadIdx.x;
    int row = idx / NQKV;
    int col = idx - row * NQKV;
    int which = col / E;
    int cc = col - which * E;
    int h = cc / A;
    int a = cc - h * A;
    int b = row / S;
    int s = row - b * S;
    size_t dst = (((size_t)h * B + b) * S + s) * A + a;
    float v = qkv[(size_t)idx];
    float* d = (which == 0) ? q : (which == 1) ? kout : vout;
    d[dst] = v;
}

// ---------------- flash-style causal attention -------------------------------
#define ALD 68
#define ATTN_SMEM (4 * 64 * ALD * 4)

__global__ __launch_bounds__(256)
void k_attn(const float* __restrict__ Qg, const float* __restrict__ Kg,
            const float* __restrict__ Vg, float* __restrict__ attn_out) {
    extern __shared__ float sm[];
    float* Qs = sm;
    float* Ks = Qs + 64 * ALD;
    float* Vs = Ks + 64 * ALD;
    float* Ps = Vs + 64 * ALD;

    int hb = blockIdx.y;
    int qt = blockIdx.x;
    int h = hb / B, b = hb - h * B;
    int q0 = qt * 64;
    int tid = threadIdx.x;

    const float4* Q4 = (const float4*)(Qg + ((size_t)hb * S + q0) * A);
#pragma unroll
    for (int i = tid; i < 64 * 16; i += 256) {
        int r = i >> 4, c = i & 15;
        *(float4*)&Qs[r * ALD + c * 4] = Q4[i];
    }

    int r = tid >> 2;
    int g = tid & 3;
    int cbase = g * 16;
    float m_run = -INFINITY, l_run = 0.f;
    float acc[16];
#pragma unroll
    for (int i = 0; i < 16; i++) acc[i] = 0.f;

    int ntiles = qt + 1;
    int qidx = q0 + r;
    const float scale = 0.03125f;

    for (int t = 0; t < ntiles; t++) {
        int k0 = t * 64;
        __syncthreads();
        const float4* K4 = (const float4*)(Kg + ((size_t)hb * S + k0) * A);
        const float4* V4 = (const float4*)(Vg + ((size_t)hb * S + k0) * A);
#pragma unroll
        for (int i = tid; i < 64 * 16; i += 256) {
            int rr = i >> 4, cc = i & 15;
            *(float4*)&Ks[rr * ALD + cc * 4] = K4[i];
            *(float4*)&Vs[rr * ALD + cc * 4] = V4[i];
        }
        __syncthreads();

        float sv[16];
#pragma unroll
        for (int i = 0; i < 16; i++) sv[i] = 0.f;
        for (int k = 0; k < 64; k += 4) {
            float4 q4 = *(const float4*)&Qs[r * ALD + k];
#pragma unroll
            for (int i = 0; i < 16; i++) {
                float4 k4 = *(const float4*)&Ks[(cbase + i) * ALD + k];
                sv[i] += q4.x * k4.x + q4.y * k4.y + q4.z * k4.z + q4.w * k4.w;
            }
        }
        float mloc = -INFINITY;
#pragma unroll
        for (int i = 0; i < 16; i++) {
            int kidx = k0 + cbase + i;
            sv[i] = (kidx <= qidx) ? sv[i] * scale : -INFINITY;
            mloc = fmaxf(mloc, sv[i]);
        }
        mloc = fmaxf(mloc, __shfl_xor_sync(0xffffffff, mloc, 1));
        mloc = fmaxf(mloc, __shfl_xor_sync(0xffffffff, mloc, 2));
        float m_new = fmaxf(m_run, mloc);
        float alpha = __expf(m_run - m_new);

        float lloc = 0.f;
        float p[16];
#pragma unroll
        for (int i = 0; i < 16; i++) { p[i] = __expf(sv[i] - m_new); lloc += p[i]; }
        lloc += __shfl_xor_sync(0xffffffff, lloc, 1);
        lloc += __shfl_xor_sync(0xffffffff, lloc, 2);
        l_run = l_run * alpha + lloc;
        m_run = m_new;
#pragma unroll
        for (int i = 0; i < 16; i++) acc[i] *= alpha;
#pragma unroll
        for (int i = 0; i < 16; i++) Ps[r * ALD + cbase + i] = p[i];
        __syncthreads();

        for (int c = 0; c < 64; c++) {
            float pv = Ps[r * ALD + c];
            const float* vrow = &Vs[c * ALD + cbase];
            float4 v0 = *(const float4*)(vrow + 0);
            float4 v1 = *(const float4*)(vrow + 4);
            float4 v2 = *(const float4*)(vrow + 8);
            float4 v3 = *(const float4*)(vrow + 12);
            acc[0]  += pv * v0.x; acc[1]  += pv * v0.y; acc[2]  += pv * v0.z; acc[3]  += pv * v0.w;
            acc[4]  += pv * v1.x; acc[5]  += pv * v1.y; acc[6]  += pv * v1.z; acc[7]  += pv * v1.w;
            acc[8]  += pv * v2.x; acc[9]  += pv * v2.y; acc[10] += pv * v2.z; acc[11] += pv * v2.w;
            acc[12] += pv * v3.x; acc[13] += pv * v3.y; acc[14] += pv * v3.z; acc[15] += pv * v3.w;
        }
    }

    float inv_l = 1.f / l_run;
    int row = b * S + q0 + r;
    float* op = attn_out + (size_t)row * E + h * A + cbase;
#pragma unroll
    for (int i = 0; i < 16; i += 4) {
        float4 o4;
        o4.x = acc[i+0] * inv_l; o4.y = acc[i+1] * inv_l;
        o4.z = acc[i+2] * inv_l; o4.w = acc[i+3] * inv_l;
        *(float4*)(op + i) = o4;
    }
}

// ---------------- LayerNorm over rows of 1024 (o = LN(a [+ b])) --------------
__global__ __launch_bounds__(256)
void k_ln(const float* __restrict__ a, const float* __restrict__ b,
          const float* __restrict__ gg, const float* __restrict__ bb,
          float* __restrict__ o) {
    __shared__ float red[16];
    __shared__ float s_mu, s_rstd;
    int row = blockIdx.x;
    int t = threadIdx.x;
    float4 x = ((const float4*)(a + (size_t)row * E))[t];
    if (b) {
        float4 y = ((const float4*)(b + (size_t)row * E))[t];
        x.x += y.x; x.y += y.y; x.z += y.z; x.w += y.w;
    }
    float sum = x.x + x.y + x.z + x.w;
    float sq  = x.x*x.x + x.y*x.y + x.z*x.z + x.w*x.w;
#pragma unroll
    for (int off = 16; off; off >>= 1) {
        sum += __shfl_xor_sync(0xffffffff, sum, off);
        sq  += __shfl_xor_sync(0xffffffff, sq,  off);
    }
    if ((t & 31) == 0) { red[t >> 5] = sum; red[8 + (t >> 5)] = sq; }
    __syncthreads();
    if (t == 0) {
        float ts = 0.f, tq = 0.f;
#pragma unroll
        for (int i = 0; i < 8; i++) { ts += red[i]; tq += red[8 + i]; }
        float mu = ts * (1.f / E);
        float var = tq * (1.f / E) - mu * mu;
        s_mu = mu; s_rstd = rsqrtf(var + 1e-5f);
    }
    __syncthreads();
    float mu = s_mu, rstd = s_rstd;
    float4 g4 = ((const float4*)gg)[t];
    float4 b4 = ((const float4*)bb)[t];
    float4 rr;
    rr.x = (x.x - mu) * rstd * g4.x + b4.x;
    rr.y = (x.y - mu) * rstd * g4.y + b4.y;
    rr.z = (x.z - mu) * rstd * g4.z + b4.z;
    rr.w = (x.w - mu) * rstd * g4.w + b4.w;
    ((float4*)(o + (size_t)row * E))[t] = rr;
}

// ---------------- launch ------------------------------------------------------
extern "C" void kernel_launch(void* const* d_in, const int* in_sizes, int n_in,
                              void* d_out, int out_size) {
    const float* emb    = (const float*)d_in[0];
    const float* pos    = (const float*)d_in[1];
    const float* Wq     = (const float*)d_in[2];
    const float* Wk     = (const float*)d_in[3];
    const float* Wv     = (const float*)d_in[4];
    const float* Wproj  = (const float*)d_in[5];
    const float* W1     = (const float*)d_in[6];
    const float* b1     = (const float*)d_in[7];
    const float* W2     = (const float*)d_in[8];
    const float* b2     = (const float*)d_in[9];
    const float* gattn  = (const float*)d_in[10];
    const float* beattn = (const float*)d_in[11];
    const float* gffn   = (const float*)d_in[12];
    const float* beffn  = (const float*)d_in[13];
    const float* gout   = (const float*)d_in[14];
    const float* beout  = (const float*)d_in[15];

    float* out  = (float*)d_out;
    float* Kout = out + (size_t)M * E;
    float* Vout = out + (size_t)2 * M * E;

    float *px, *pwT, *pqkv, *pq, *pattn, *pmha, *phid, *pff, *pffout;
    cudaGetSymbolAddress((void**)&px,    g_x);
    cudaGetSymbolAddress((void**)&pwT,   g_wqkvT);
    cudaGetSymbolAddress((void**)&pqkv,  g_qkv);
    cudaGetSymbolAddress((void**)&pq,    g_q);
    cudaGetSymbolAddress((void**)&pattn, g_attn);
    cudaGetSymbolAddress((void**)&pmha,  g_mha);
    cudaGetSymbolAddress((void**)&phid,  g_hidden);
    cudaGetSymbolAddress((void**)&pff,   g_ff);
    cudaGetSymbolAddress((void**)&pffout,g_ffout);

    cudaFuncSetAttribute(k_attn, cudaFuncAttributeMaxDynamicSharedMemorySize,
                         ATTN_SMEM);

    k_add<<<(M * E / 4) / 256, 256>>>((const float4*)emb, (const float4*)pos,
                                      (float4*)px);
    k_wqkv<<<(3 * E * E) / 256, 256>>>(Wq, Wk, Wv, pwT);
    {
        dim3 grid(NQKV / BN, M / BM);
        k_gemm<<<grid, 256>>>(px, pwT, pqkv, M, NQKV, E, nullptr, nullptr, 0);
    }
    k_scatter<<<(M * NQKV) / 256, 256>>>(pqkv, pq, Kout, Vout);
    {
        dim3 grid(S / 64, H * B);
        k_attn<<<grid, 256, ATTN_SMEM>>>(pq, Kout, Vout, pattn);
    }
    {
        dim3 grid(E / BN, M / BM);
        k_gemm<<<grid, 256>>>(pattn, Wproj, pqkv, M, E, E, nullptr, px, 0);
    }
    k_ln<<<M, 256>>>(pqkv, nullptr, gattn, beattn, pmha);
    {
        dim3 grid(FFD / BN, M / BM);
        k_gemm<<<grid, 256>>>(pmha, W1, phid, M, FFD, E, b1, nullptr, 0);
    }
    {
        dim3 grid(E / BN, M / BM);
        k_gemm<<<grid, 256>>>(phid, W2, pff, M, E, FFD, b2, nullptr, 1);
    }
    k_ln<<<M, 256>>>(pmha, pff, gffn, beffn, pffout);
    k_ln<<<M, 256>>>(pmha, pffout, gout, beout, out);
}

// round 3
// speedup vs baseline: 1.3772x; 1.3772x over previous
#include <cuda_runtime.h>
#include <math.h>

// Problem constants
#define E   1024
#define A   64
#define H   16
#define FFD 4096
#define B   2
#define S   2048
#define M   (B*S)        // 4096 rows
#define NQKV (3*E)       // 3072

// ---------------- scratch (device globals) -----------------------------------
__device__ float g_x[M*E];
__device__ float g_wqkvT[E*NQKV];
__device__ float g_qkv[M*NQKV];
__device__ float g_q[H*B*S*A];
__device__ float g_attn[M*E];
__device__ float g_mha[M*E];
__device__ float g_hidden[M*FFD];
__device__ float g_ff[M*E];
__device__ float g_ffout[M*E];

// ---------------- elementwise add --------------------------------------------
__global__ void k_add(const float4* __restrict__ a, const float4* __restrict__ b,
                      float4* __restrict__ o) {
    int i = blockIdx.x * blockDim.x + threadIdx.x;
    float4 x = a[i], y = b[i];
    x.x += y.x; x.y += y.y; x.z += y.z; x.w += y.w;
    o[i] = x;
}

// ---------------- fuse Wq/Wk/Wv [H,E,A] -> [E, 3E] ---------------------------
__global__ void k_wqkv(const float* __restrict__ Wq, const float* __restrict__ Wk,
                       const float* __restrict__ Wv, float* __restrict__ out) {
    int idx = blockIdx.x * blockDim.x + threadIdx.x;
    int qkv = idx / (E*E);
    int rem = idx - qkv * (E*E);
    int h = rem / (E*A);
    int ea = rem - h * (E*A);
    int e = ea / A;
    int a = ea - e * A;
    const float* W = (qkv == 0) ? Wq : (qkv == 1) ? Wk : Wv;
    out[(size_t)e * NQKV + qkv * E + h * A + a] = W[rem];
}

// ---------------- tf32 tensor-core GEMM 128x128x16 ---------------------------
// 256 threads = 8 warps (2 M x 4 N), warp tile 64x32, mma.m16n8k8.tf32
#define GP 20     // A smem pitch (conflict-free fragment loads)
#define BP 136    // B smem pitch (conflict-free fragment loads)

__device__ __forceinline__ float ftf32(float x) {
    float y;
    asm("cvt.rna.tf32.f32 %0, %1;" : "=f"(y) : "f"(x));
    return y;
}

__global__ __launch_bounds__(256, 2)
void k_gemm_tc(const float* __restrict__ Ag, const float* __restrict__ Bg,
               float* __restrict__ Cg, int Nd, int Kd,
               const float* __restrict__ bias, const float* __restrict__ resid,
               int do_relu) {
    __shared__ float As[2][128][GP];   // [m][k] tf32
    __shared__ float Bs[2][16][BP];    // [k][n] tf32

    int tid  = threadIdx.x;
    int lane = tid & 31, wid = tid >> 5;
    int wm = wid & 1, wn = wid >> 1;         // warp position
    int gid = lane >> 2, qid = lane & 3;

    const float* Ab = Ag + (size_t)blockIdx.y * 128 * Kd;
    const float* Bb = Bg + blockIdx.x * 128;

    // global load mapping
    int ar = tid >> 2;                 // A rows: ar, ar+64
    int ac = (tid & 3) * 4;            // A k-cols (float4)
    int bk = tid >> 5;                 // B k-rows: bk, bk+8
    int bc = (tid & 31) * 4;           // B n-cols (float4)

    float acc[4][4][4];
#pragma unroll
    for (int i = 0; i < 4; i++)
#pragma unroll
        for (int j = 0; j < 4; j++)
#pragma unroll
            for (int r = 0; r < 4; r++) acc[i][j][r] = 0.f;

    float4 va0, va1, vb0, vb1;
    // prologue
    va0 = *(const float4*)(Ab + (size_t)ar * Kd + ac);
    va1 = *(const float4*)(Ab + (size_t)(ar + 64) * Kd + ac);
    vb0 = *(const float4*)(Bb + (size_t)bk * Nd + bc);
    vb1 = *(const float4*)(Bb + (size_t)(bk + 8) * Nd + bc);
    As[0][ar][ac+0] = ftf32(va0.x); As[0][ar][ac+1] = ftf32(va0.y);
    As[0][ar][ac+2] = ftf32(va0.z); As[0][ar][ac+3] = ftf32(va0.w);
    As[0][ar+64][ac+0] = ftf32(va1.x); As[0][ar+64][ac+1] = ftf32(va1.y);
    As[0][ar+64][ac+2] = ftf32(va1.z); As[0][ar+64][ac+3] = ftf32(va1.w);
    Bs[0][bk][bc+0] = ftf32(vb0.x); Bs[0][bk][bc+1] = ftf32(vb0.y);
    Bs[0][bk][bc+2] = ftf32(vb0.z); Bs[0][bk][bc+3] = ftf32(vb0.w);
    Bs[0][bk+8][bc+0] = ftf32(vb1.x); Bs[0][bk+8][bc+1] = ftf32(vb1.y);
    Bs[0][bk+8][bc+2] = ftf32(vb1.z); Bs[0][bk+8][bc+3] = ftf32(vb1.w);
    __syncthreads();

    int buf = 0;
    for (int k0 = 16; ; k0 += 16) {
        bool more = (k0 < Kd);
        if (more) {
            va0 = *(const float4*)(Ab + (size_t)ar * Kd + k0 + ac);
            va1 = *(const float4*)(Ab + (size_t)(ar + 64) * Kd + k0 + ac);
            vb0 = *(const float4*)(Bb + (size_t)(k0 + bk) * Nd + bc);
            vb1 = *(const float4*)(Bb + (size_t)(k0 + bk + 8) * Nd + bc);
        }
#pragma unroll
        for (int ks = 0; ks < 16; ks += 8) {
            unsigned af[4][4], bf[4][2];
#pragma unroll
            for (int mi = 0; mi < 4; mi++) {
                int row = wm * 64 + mi * 16 + gid;
                af[mi][0] = __float_as_uint(As[buf][row][ks + qid]);
                af[mi][1] = __float_as_uint(As[buf][row + 8][ks + qid]);
                af[mi][2] = __float_as_uint(As[buf][row][ks + qid + 4]);
                af[mi][3] = __float_as_uint(As[buf][row + 8][ks + qid + 4]);
            }
#pragma unroll
            for (int ni = 0; ni < 4; ni++) {
                int col = wn * 32 + ni * 8 + gid;
                bf[ni][0] = __float_as_uint(Bs[buf][ks + qid][col]);
                bf[ni][1] = __float_as_uint(Bs[buf][ks + qid + 4][col]);
            }
#pragma unroll
            for (int mi = 0; mi < 4; mi++)
#pragma unroll
                for (int ni = 0; ni < 4; ni++) {
                    asm volatile(
                        "mma.sync.aligned.m16n8k8.row.col.f32.tf32.tf32.f32 "
                        "{%0,%1,%2,%3}, {%4,%5,%6,%7}, {%8,%9}, {%0,%1,%2,%3};"
                        : "+f"(acc[mi][ni][0]), "+f"(acc[mi][ni][1]),
                          "+f"(acc[mi][ni][2]), "+f"(acc[mi][ni][3])
                        : "r"(af[mi][0]), "r"(af[mi][1]),
                          "r"(af[mi][2]), "r"(af[mi][3]),
                          "r"(bf[ni][0]), "r"(bf[ni][1]));
                }
        }
        if (!more) break;
        int nb = buf ^ 1;
        As[nb][ar][ac+0] = ftf32(va0.x); As[nb][ar][ac+1] = ftf32(va0.y);
        As[nb][ar][ac+2] = ftf32(va0.z); As[nb][ar][ac+3] = ftf32(va0.w);
        As[nb][ar+64][ac+0] = ftf32(va1.x); As[nb][ar+64][ac+1] = ftf32(va1.y);
        As[nb][ar+64][ac+2] = ftf32(va1.z); As[nb][ar+64][ac+3] = ftf32(va1.w);
        Bs[nb][bk][bc+0] = ftf32(vb0.x); Bs[nb][bk][bc+1] = ftf32(vb0.y);
        Bs[nb][bk][bc+2] = ftf32(vb0.z); Bs[nb][bk][bc+3] = ftf32(vb0.w);
        Bs[nb][bk+8][bc+0] = ftf32(vb1.x); Bs[nb][bk+8][bc+1] = ftf32(vb1.y);
        Bs[nb][bk+8][bc+2] = ftf32(vb1.z); Bs[nb][bk+8][bc+3] = ftf32(vb1.w);
        __syncthreads();
        buf = nb;
    }

    // epilogue
    int bn = blockIdx.x * 128;
#pragma unroll
    for (int mi = 0; mi < 4; mi++) {
        int r0 = blockIdx.y * 128 + wm * 64 + mi * 16 + gid;
        int r1 = r0 + 8;
#pragma unroll
        for (int ni = 0; ni < 4; ni++) {
            int col = bn + wn * 32 + ni * 8 + 2 * qid;
            float2 v0 = make_float2(acc[mi][ni][0], acc[mi][ni][1]);
            float2 v1 = make_float2(acc[mi][ni][2], acc[mi][ni][3]);
            if (bias) {
                float2 bb = *(const float2*)(bias + col);
                v0.x += bb.x; v0.y += bb.y; v1.x += bb.x; v1.y += bb.y;
            }
            if (resid) {
                float2 q0 = *(const float2*)(resid + (size_t)r0 * Nd + col);
                float2 q1 = *(const float2*)(resid + (size_t)r1 * Nd + col);
                v0.x += q0.x; v0.y += q0.y; v1.x += q1.x; v1.y += q1.y;
            }
            if (do_relu) {
                v0.x = fmaxf(v0.x, 0.f); v0.y = fmaxf(v0.y, 0.f);
                v1.x = fmaxf(v1.x, 0.f); v1.y = fmaxf(v1.y, 0.f);
            }
            *(float2*)(Cg + (size_t)r0 * Nd + col) = v0;
            *(float2*)(Cg + (size_t)r1 * Nd + col) = v1;
        }
    }
}

// ---------------- scatter fused qkv -> Q scratch, K/V into d_out -------------
__global__ void k_scatter(const float* __restrict__ qkv, float* __restrict__ q,
                          float* __restrict__ kout, float* __restrict__ vout) {
    int idx = blockIdx.x * blockDim.x + threadIdx.x;
    int row = idx / NQKV;
    int col = idx - row * NQKV;
    int which = col / E;
    int cc = col - which * E;
    int h = cc / A;
    int a = cc - h * A;
    int b = row / S;
    int s = row - b * S;
    size_t dst = (((size_t)h * B + b) * S + s) * A + a;
    float v = qkv[(size_t)idx];
    float* d = (which == 0) ? q : (which == 1) ? kout : vout;
    d[dst] = v;
}

// ---------------- flash-style causal attention --------------------------------
#define ALD 68
#define ATTN_SMEM (4 * 64 * ALD * 4)

__global__ __launch_bounds__(256)
void k_attn(const float* __restrict__ Qg, const float* __restrict__ Kg,
            const float* __restrict__ Vg, float* __restrict__ attn_out) {
    extern __shared__ float sm[];
    float* Qs = sm;
    float* Ks = Qs + 64 * ALD;
    float* Vs = Ks + 64 * ALD;
    float* Ps = Vs + 64 * ALD;

    int hb = blockIdx.y;
    int qt = blockIdx.x;
    int h = hb / B, b = hb - h * B;
    int q0 = qt * 64;
    int tid = threadIdx.x;

    const float4* Q4 = (const float4*)(Qg + ((size_t)hb * S + q0) * A);
#pragma unroll
    for (int i = tid; i < 64 * 16; i += 256) {
        int r = i >> 4, c = i & 15;
        *(float4*)&Qs[r * ALD + c * 4] = Q4[i];
    }

    int r = tid >> 2;
    int g = tid & 3;
    int cbase = g * 16;
    float m_run = -INFINITY, l_run = 0.f;
    float acc[16];
#pragma unroll
    for (int i = 0; i < 16; i++) acc[i] = 0.f;

    int ntiles = qt + 1;
    int qidx = q0 + r;
    const float scale = 0.03125f;

    for (int t = 0; t < ntiles; t++) {
        int k0 = t * 64;
        __syncthreads();
        const float4* K4 = (const float4*)(Kg + ((size_t)hb * S + k0) * A);
        const float4* V4 = (const float4*)(Vg + ((size_t)hb * S + k0) * A);
#pragma unroll
        for (int i = tid; i < 64 * 16; i += 256) {
            int rr = i >> 4, cc = i & 15;
            *(float4*)&Ks[rr * ALD + cc * 4] = K4[i];
            *(float4*)&Vs[rr * ALD + cc * 4] = V4[i];
        }
        __syncthreads();

        float sv[16];
#pragma unroll
        for (int i = 0; i < 16; i++) sv[i] = 0.f;
        for (int k = 0; k < 64; k += 4) {
            float4 q4 = *(const float4*)&Qs[r * ALD + k];
#pragma unroll
            for (int i = 0; i < 16; i++) {
                float4 k4 = *(const float4*)&Ks[(cbase + i) * ALD + k];
                sv[i] += q4.x * k4.x + q4.y * k4.y + q4.z * k4.z + q4.w * k4.w;
            }
        }
        float mloc = -INFINITY;
#pragma unroll
        for (int i = 0; i < 16; i++) {
            int kidx = k0 + cbase + i;
            sv[i] = (kidx <= qidx) ? sv[i] * scale : -INFINITY;
            mloc = fmaxf(mloc, sv[i]);
        }
        mloc = fmaxf(mloc, __shfl_xor_sync(0xffffffff, mloc, 1));
        mloc = fmaxf(mloc, __shfl_xor_sync(0xffffffff, mloc, 2));
        float m_new = fmaxf(m_run, mloc);
        float alpha = __expf(m_run - m_new);

        float lloc = 0.f;
        float p[16];
#pragma unroll
        for (int i = 0; i < 16; i++) { p[i] = __expf(sv[i] - m_new); lloc += p[i]; }
        lloc += __shfl_xor_sync(0xffffffff, lloc, 1);
        lloc += __shfl_xor_sync(0xffffffff, lloc, 2);
        l_run = l_run * alpha + lloc;
        m_run = m_new;
#pragma unroll
        for (int i = 0; i < 16; i++) acc[i] *= alpha;
#pragma unroll
        for (int i = 0; i < 16; i++) Ps[r * ALD + cbase + i] = p[i];
        __syncthreads();

        for (int c = 0; c < 64; c++) {
            float pv = Ps[r * ALD + c];
            const float* vrow = &Vs[c * ALD + cbase];
            float4 v0 = *(const float4*)(vrow + 0);
            float4 v1 = *(const float4*)(vrow + 4);
            float4 v2 = *(const float4*)(vrow + 8);
            float4 v3 = *(const float4*)(vrow + 12);
            acc[0]  += pv * v0.x; acc[1]  += pv * v0.y; acc[2]  += pv * v0.z; acc[3]  += pv * v0.w;
            acc[4]  += pv * v1.x; acc[5]  += pv * v1.y; acc[6]  += pv * v1.z; acc[7]  += pv * v1.w;
            acc[8]  += pv * v2.x; acc[9]  += pv * v2.y; acc[10] += pv * v2.z; acc[11] += pv * v2.w;
            acc[12] += pv * v3.x; acc[13] += pv * v3.y; acc[14] += pv * v3.z; acc[15] += pv * v3.w;
        }
    }

    float inv_l = 1.f / l_run;
    int row = b * S + q0 + r;
    float* op = attn_out + (size_t)row * E + h * A + cbase;
#pragma unroll
    for (int i = 0; i < 16; i += 4) {
        float4 o4;
        o4.x = acc[i+0] * inv_l; o4.y = acc[i+1] * inv_l;
        o4.z = acc[i+2] * inv_l; o4.w = acc[i+3] * inv_l;
        *(float4*)(op + i) = o4;
    }
}

// ---------------- LayerNorm over rows of 1024 ---------------------------------
__global__ __launch_bounds__(256)
void k_ln(const float* __restrict__ a, const float* __restrict__ b,
          const float* __restrict__ gg, const float* __restrict__ bb,
          float* __restrict__ o) {
    __shared__ float red[16];
    __shared__ float s_mu, s_rstd;
    int row = blockIdx.x;
    int t = threadIdx.x;
    float4 x = ((const float4*)(a + (size_t)row * E))[t];
    if (b) {
        float4 y = ((const float4*)(b + (size_t)row * E))[t];
        x.x += y.x; x.y += y.y; x.z += y.z; x.w += y.w;
    }
    float sum = x.x + x.y + x.z + x.w;
    float sq  = x.x*x.x + x.y*x.y + x.z*x.z + x.w*x.w;
#pragma unroll
    for (int off = 16; off; off >>= 1) {
        sum += __shfl_xor_sync(0xffffffff, sum, off);
        sq  += __shfl_xor_sync(0xffffffff, sq,  off);
    }
    if ((t & 31) == 0) { red[t >> 5] = sum; red[8 + (t >> 5)] = sq; }
    __syncthreads();
    if (t == 0) {
        float ts = 0.f, tq = 0.f;
#pragma unroll
        for (int i = 0; i < 8; i++) { ts += red[i]; tq += red[8 + i]; }
        float mu = ts * (1.f / E);
        float var = tq * (1.f / E) - mu * mu;
        s_mu = mu; s_rstd = rsqrtf(var + 1e-5f);
    }
    __syncthreads();
    float mu = s_mu, rstd = s_rstd;
    float4 g4 = ((const float4*)gg)[t];
    float4 b4 = ((const float4*)bb)[t];
    float4 rr;
    rr.x = (x.x - mu) * rstd * g4.x + b4.x;
    rr.y = (x.y - mu) * rstd * g4.y + b4.y;
    rr.z = (x.z - mu) * rstd * g4.z + b4.z;
    rr.w = (x.w - mu) * rstd * g4.w + b4.w;
    ((float4*)(o + (size_t)row * E))[t] = rr;
}

// ---------------- launch -------------------------------------------------------
extern "C" void kernel_launch(void* const* d_in, const int* in_sizes, int n_in,
                              void* d_out, int out_size) {
    const float* emb    = (const float*)d_in[0];
    const float* pos    = (const float*)d_in[1];
    const float* Wq     = (const float*)d_in[2];
    const float* Wk     = (const float*)d_in[3];
    const float* Wv     = (const float*)d_in[4];
    const float* Wproj  = (const float*)d_in[5];
    const float* W1     = (const float*)d_in[6];
    const float* b1     = (const float*)d_in[7];
    const float* W2     = (const float*)d_in[8];
    const float* b2     = (const float*)d_in[9];
    const float* gattn  = (const float*)d_in[10];
    const float* beattn = (const float*)d_in[11];
    const float* gffn   = (const float*)d_in[12];
    const float* beffn  = (const float*)d_in[13];
    const float* gout   = (const float*)d_in[14];
    const float* beout  = (const float*)d_in[15];

    float* out  = (float*)d_out;
    float* Kout = out + (size_t)M * E;
    float* Vout = out + (size_t)2 * M * E;

    float *px, *pwT, *pqkv, *pq, *pattn, *pmha, *phid, *pff, *pffout;
    cudaGetSymbolAddress((void**)&px,    g_x);
    cudaGetSymbolAddress((void**)&pwT,   g_wqkvT);
    cudaGetSymbolAddress((void**)&pqkv,  g_qkv);
    cudaGetSymbolAddress((void**)&pq,    g_q);
    cudaGetSymbolAddress((void**)&pattn, g_attn);
    cudaGetSymbolAddress((void**)&pmha,  g_mha);
    cudaGetSymbolAddress((void**)&phid,  g_hidden);
    cudaGetSymbolAddress((void**)&pff,   g_ff);
    cudaGetSymbolAddress((void**)&pffout,g_ffout);

    cudaFuncSetAttribute(k_attn, cudaFuncAttributeMaxDynamicSharedMemorySize,
                         ATTN_SMEM);

    k_add<<<(M * E / 4) / 256, 256>>>((const float4*)emb, (const float4*)pos,
                                      (float4*)px);
    k_wqkv<<<(3 * E * E) / 256, 256>>>(Wq, Wk, Wv, pwT);
    {
        dim3 grid(NQKV / 128, M / 128);
        k_gemm_tc<<<grid, 256>>>(px, pwT, pqkv, NQKV, E, nullptr, nullptr, 0);
    }
    k_scatter<<<(M * NQKV) / 256, 256>>>(pqkv, pq, Kout, Vout);
    {
        dim3 grid(S / 64, H * B);
        k_attn<<<grid, 256, ATTN_SMEM>>>(pq, Kout, Vout, pattn);
    }
    {
        dim3 grid(E / 128, M / 128);
        k_gemm_tc<<<grid, 256>>>(pattn, Wproj, pqkv, E, E, nullptr, px, 0);
    }
    k_ln<<<M, 256>>>(pqkv, nullptr, gattn, beattn, pmha);
    {
        dim3 grid(FFD / 128, M / 128);
        k_gemm_tc<<<grid, 256>>>(pmha, W1, phid, FFD, E, b1, nullptr, 0);
    }
    {
        dim3 grid(E / 128, M / 128);
        k_gemm_tc<<<grid, 256>>>(phid, W2, pff, E, FFD, b2, nullptr, 1);
    }
    k_ln<<<M, 256>>>(pmha, pff, gffn, beffn, pffout);
    k_ln<<<M, 256>>>(pmha, pffout, gout, beout, out);
}